// round 1
// baseline (speedup 1.0000x reference)
#include <cuda_runtime.h>
#include <math.h>
#include <stdint.h>

// Problem constants
#define NB   2
#define NS   2048
#define ND   1024
#define NH   16
#define NHD  64
#define NBH  (NB*NH)       // 32
#define NM   (NB*NS)       // 4096 rows for projections
#define OUT_ELEMS  (NB*NS*ND)                       // 4,194,304
#define ATTN_ELEMS ((long long)NBH*(long long)NS*NS) // 134,217,728

#define NEG_INF __int_as_float(0xff800000)

// ---- scratch (device globals; no runtime allocation allowed) ----
__device__ float g_q[NBH * NS * NHD];
__device__ float g_k[NBH * NS * NHD];
__device__ float g_v[NBH * NS * NHD];
__device__ float g_ctx[NBH * NS * NHD];
__device__ float g_attn_scratch[134217728]; // fallback if out buffer excludes attn
__device__ int   g_mask_is_u8;

// ---------------------------------------------------------------------------
// Mask dtype detection: mask row 0 is all-true (global tokens).
// element[1] as byte: u8 -> 1 ; int32 little-endian -> 0 (high byte of elem 0)
// ---------------------------------------------------------------------------
__global__ void detect_mask_kernel(const unsigned char* __restrict__ m) {
    g_mask_is_u8 = (m[1] != 0) ? 1 : 0;
}

// ---------------------------------------------------------------------------
// Generic 64x64-tile SGEMM for M=4096, N=K=1024:  C = A @ W + bias
// gatherA: A is read from BHSD-layout ctx tensor
// scatterC: C is written to BHSD layout (for q/k/v)
// ---------------------------------------------------------------------------
__global__ void gemm1024_kernel(const float* __restrict__ A,
                                const float* __restrict__ W,
                                const float* __restrict__ bias,
                                float* __restrict__ C,
                                int gatherA, int scatterC)
{
    __shared__ float As[16][64];   // [k][m]
    __shared__ float Bs[16][64];   // [k][n]

    const int tid = threadIdx.x;          // 256 threads
    const int tx  = tid & 15;
    const int ty  = tid >> 4;
    const int row0 = blockIdx.y * 64;
    const int col0 = blockIdx.x * 64;

    float acc[4][4] = {};

    for (int k0 = 0; k0 < ND; k0 += 16) {
        // load A tile (64 rows x 16 k) -- coalesced 16-wide rows
        #pragma unroll
        for (int i = 0; i < 4; i++) {
            int idx = i * 256 + tid;
            int r = idx >> 4;           // m in tile
            int c = idx & 15;           // k in tile
            int gr = row0 + r;
            int gk = k0 + c;
            float aval;
            if (gatherA) {
                int b = gr >> 11;        // / NS
                int s = gr & (NS - 1);
                int h = gk >> 6;
                int d = gk & 63;
                aval = A[(((size_t)(b * NH + h)) * NS + s) * NHD + d];
            } else {
                aval = A[(size_t)gr * ND + gk];
            }
            As[c][r] = aval;
        }
        // load W tile (16 k x 64 n) -- fully coalesced
        #pragma unroll
        for (int i = 0; i < 4; i++) {
            int idx = i * 256 + tid;
            int r = idx >> 6;
            int c = idx & 63;
            Bs[r][c] = W[(size_t)(k0 + r) * ND + col0 + c];
        }
        __syncthreads();

        #pragma unroll
        for (int kk = 0; kk < 16; kk++) {
            float4 av = *(const float4*)&As[kk][ty * 4];
            float4 bv = *(const float4*)&Bs[kk][tx * 4];
            float a[4] = {av.x, av.y, av.z, av.w};
            float b[4] = {bv.x, bv.y, bv.z, bv.w};
            #pragma unroll
            for (int i = 0; i < 4; i++)
                #pragma unroll
                for (int j = 0; j < 4; j++)
                    acc[i][j] = fmaf(a[i], b[j], acc[i][j]);
        }
        __syncthreads();
    }

    #pragma unroll
    for (int i = 0; i < 4; i++) {
        int m = row0 + ty * 4 + i;
        if (scatterC) {
            int b = m >> 11;
            int s = m & (NS - 1);
            #pragma unroll
            for (int j = 0; j < 4; j++) {
                int n = col0 + tx * 4 + j;
                int h = n >> 6;
                int d = n & 63;
                C[(((size_t)(b * NH + h)) * NS + s) * NHD + d] = acc[i][j] + bias[n];
            }
        } else {
            float4 o;
            int n = col0 + tx * 4;
            o.x = acc[i][0] + bias[n + 0];
            o.y = acc[i][1] + bias[n + 1];
            o.z = acc[i][2] + bias[n + 2];
            o.w = acc[i][3] + bias[n + 3];
            *(float4*)&C[(size_t)m * ND + n] = o;
        }
    }
}

// ---------------------------------------------------------------------------
// Scores: attn[bh, q, k] = mask ? (Q . K) * scale : -inf
// grid = (ktile=32, qtile=32, bh=32), block = 256
// ---------------------------------------------------------------------------
__global__ void score_kernel(const float* __restrict__ qg,
                             const float* __restrict__ kg,
                             const unsigned char* __restrict__ mask8,
                             float* __restrict__ attn)
{
    __shared__ float Qt[64][68];  // [d][m]
    __shared__ float Kt[64][68];  // [d][n]

    const int tid = threadIdx.x;
    const int tx  = tid & 15;
    const int ty  = tid >> 4;
    const int kt  = blockIdx.x;
    const int qt  = blockIdx.y;
    const int bh  = blockIdx.z;

    const float* q = qg + (size_t)bh * NS * NHD;
    const float* k = kg + (size_t)bh * NS * NHD;

    #pragma unroll
    for (int i = 0; i < 16; i++) {
        int idx = i * 256 + tid;
        int r = idx >> 6;       // row within tile
        int c = idx & 63;       // d
        Qt[c][r] = q[(size_t)(qt * 64 + r) * NHD + c];
        Kt[c][r] = k[(size_t)(kt * 64 + r) * NHD + c];
    }
    __syncthreads();

    float acc[4][4] = {};
    #pragma unroll 8
    for (int d = 0; d < 64; d++) {
        float4 av = *(const float4*)&Qt[d][ty * 4];
        float4 bv = *(const float4*)&Kt[d][tx * 4];
        float a[4] = {av.x, av.y, av.z, av.w};
        float b[4] = {bv.x, bv.y, bv.z, bv.w};
        #pragma unroll
        for (int i = 0; i < 4; i++)
            #pragma unroll
            for (int j = 0; j < 4; j++)
                acc[i][j] = fmaf(a[i], b[j], acc[i][j]);
    }

    const float scale = 0.125f;  // 1/sqrt(64)
    const int use8 = g_mask_is_u8;
    const int* mask32 = (const int*)mask8;

    #pragma unroll
    for (int i = 0; i < 4; i++) {
        int qr = qt * 64 + ty * 4 + i;
        size_t mbase = (size_t)qr * NS + kt * 64 + tx * 4;
        float vals[4];
        #pragma unroll
        for (int j = 0; j < 4; j++) {
            bool mv = use8 ? (mask8[mbase + j] != 0) : (mask32[mbase + j] != 0);
            vals[j] = mv ? acc[i][j] * scale : NEG_INF;
        }
        float4 o = {vals[0], vals[1], vals[2], vals[3]};
        *(float4*)&attn[((size_t)bh * NS + qr) * NS + kt * 64 + tx * 4] = o;
    }
}

// ---------------------------------------------------------------------------
// Row softmax over 2048 elements, in place. grid = 65536 rows, block = 256.
// ---------------------------------------------------------------------------
__global__ void softmax_kernel(float* __restrict__ attn)
{
    const size_t row = blockIdx.x;
    float* p = attn + row * (size_t)NS;
    const int tid = threadIdx.x;

    float v[8];
    float mx = NEG_INF;
    #pragma unroll
    for (int i = 0; i < 8; i++) {
        v[i] = p[tid + i * 256];
        mx = fmaxf(mx, v[i]);
    }

    __shared__ float sh[8];
    #pragma unroll
    for (int o = 16; o > 0; o >>= 1)
        mx = fmaxf(mx, __shfl_xor_sync(0xffffffffu, mx, o));
    if ((tid & 31) == 0) sh[tid >> 5] = mx;
    __syncthreads();
    if (tid < 32) {
        float m2 = (tid < 8) ? sh[tid] : NEG_INF;
        #pragma unroll
        for (int o = 4; o > 0; o >>= 1)
            m2 = fmaxf(m2, __shfl_xor_sync(0xffffffffu, m2, o));
        if (tid == 0) sh[0] = m2;
    }
    __syncthreads();
    mx = sh[0];
    __syncthreads();

    float s = 0.0f;
    #pragma unroll
    for (int i = 0; i < 8; i++) {
        v[i] = __expf(v[i] - mx);   // exp(-inf) = 0 for masked entries
        s += v[i];
    }
    #pragma unroll
    for (int o = 16; o > 0; o >>= 1)
        s += __shfl_xor_sync(0xffffffffu, s, o);
    if ((tid & 31) == 0) sh[tid >> 5] = s;
    __syncthreads();
    if (tid < 32) {
        float s2 = (tid < 8) ? sh[tid] : 0.0f;
        #pragma unroll
        for (int o = 4; o > 0; o >>= 1)
            s2 += __shfl_xor_sync(0xffffffffu, s2, o);
        if (tid == 0) sh[0] = s2;
    }
    __syncthreads();
    const float inv = 1.0f / sh[0];

    #pragma unroll
    for (int i = 0; i < 8; i++)
        p[tid + i * 256] = v[i] * inv;
}

// ---------------------------------------------------------------------------
// PV: ctx[bh, q, d] = sum_k attn[bh,q,k] * V[bh,k,d]
// grid = (qtile=32, bh=32), block = 256
// ---------------------------------------------------------------------------
__global__ void av_kernel(const float* __restrict__ attn,
                          const float* __restrict__ vg,
                          float* __restrict__ ctx)
{
    __shared__ float Pt[64][68];  // [k][q]
    __shared__ float Vs[64][64];  // [k][d]

    const int tid = threadIdx.x;
    const int tx  = tid & 15;
    const int ty  = tid >> 4;
    const int qt  = blockIdx.x;
    const int bh  = blockIdx.y;

    const float* v    = vg + (size_t)bh * NS * NHD;
    const float* prow = attn + ((size_t)bh * NS + qt * 64) * NS;

    float acc[4][4] = {};

    for (int k0 = 0; k0 < NS; k0 += 64) {
        #pragma unroll
        for (int i = 0; i < 16; i++) {
            int idx = i * 256 + tid;
            int r = idx >> 6;
            int c = idx & 63;
            Pt[c][r] = prow[(size_t)r * NS + k0 + c];
            Vs[r][c] = v[(size_t)(k0 + r) * NHD + c];
        }
        __syncthreads();

        #pragma unroll 8
        for (int kk = 0; kk < 64; kk++) {
            float4 av = *(const float4*)&Pt[kk][ty * 4];
            float4 bv = *(const float4*)&Vs[kk][tx * 4];
            float a[4] = {av.x, av.y, av.z, av.w};
            float b[4] = {bv.x, bv.y, bv.z, bv.w};
            #pragma unroll
            for (int i = 0; i < 4; i++)
                #pragma unroll
                for (int j = 0; j < 4; j++)
                    acc[i][j] = fmaf(a[i], b[j], acc[i][j]);
        }
        __syncthreads();
    }

    #pragma unroll
    for (int i = 0; i < 4; i++) {
        float4 o = {acc[i][0], acc[i][1], acc[i][2], acc[i][3]};
        *(float4*)&ctx[((size_t)bh * NS + qt * 64 + ty * 4 + i) * NHD + tx * 4] = o;
    }
}

// ---------------------------------------------------------------------------
extern "C" void kernel_launch(void* const* d_in, const int* in_sizes, int n_in,
                              void* d_out, int out_size)
{
    (void)in_sizes; (void)n_in;

    const float* query = (const float*)d_in[0];
    const float* key   = (const float*)d_in[1];
    const float* value = (const float*)d_in[2];
    const float* Wq    = (const float*)d_in[3];
    const float* bq    = (const float*)d_in[4];
    const float* Wk    = (const float*)d_in[5];
    const float* bk    = (const float*)d_in[6];
    const float* Wv    = (const float*)d_in[7];
    const float* bv    = (const float*)d_in[8];
    const float* Wo    = (const float*)d_in[9];
    const float* bo    = (const float*)d_in[10];
    const unsigned char* mask = (const unsigned char*)d_in[11];

    float* out = (float*)d_out;

    // scratch symbol addresses (host-side queries; no allocation)
    float *qp, *kp, *vp, *ctxp, *attn;
    cudaGetSymbolAddress((void**)&qp,   g_q);
    cudaGetSymbolAddress((void**)&kp,   g_k);
    cudaGetSymbolAddress((void**)&vp,   g_v);
    cudaGetSymbolAddress((void**)&ctxp, g_ctx);

    if ((long long)out_size >= (long long)OUT_ELEMS + ATTN_ELEMS) {
        attn = out + OUT_ELEMS;             // harness output = concat(out, attn)
    } else {
        cudaGetSymbolAddress((void**)&attn, g_attn_scratch);
    }

    detect_mask_kernel<<<1, 1>>>(mask);

    dim3 blk(256);
    dim3 gproj(ND / 64, NM / 64);  // (16, 64)
    gemm1024_kernel<<<gproj, blk>>>(query, Wq, bq, qp, 0, 1);
    gemm1024_kernel<<<gproj, blk>>>(key,   Wk, bk, kp, 0, 1);
    gemm1024_kernel<<<gproj, blk>>>(value, Wv, bv, vp, 0, 1);

    dim3 gscore(NS / 64, NS / 64, NBH);    // (32, 32, 32)
    score_kernel<<<gscore, blk>>>(qp, kp, mask, attn);

    softmax_kernel<<<NBH * NS, blk>>>(attn);

    dim3 gav(NS / 64, NBH);                // (32, 32)
    av_kernel<<<gav, blk>>>(attn, vp, ctxp);

    gemm1024_kernel<<<gproj, blk>>>(ctxp, Wo, bo, out, 1, 0);
}

// round 2
// speedup vs baseline: 1.3990x; 1.3990x over previous
#include <cuda_runtime.h>
#include <math.h>
#include <stdint.h>

// Problem constants
#define NB   2
#define NS   2048
#define ND   1024
#define NH   16
#define NHD  64
#define NBH  (NB*NH)       // 32
#define NM   (NB*NS)       // 4096 rows for projections
#define OUT_ELEMS  (NB*NS*ND)                        // 4,194,304
#define ATTN_ELEMS ((long long)NBH*(long long)NS*NS) // 134,217,728

#define NEG_INF __int_as_float(0xff800000)

// ---- scratch (device globals; no runtime allocation allowed) ----
__device__ float g_q[NBH * NS * NHD];
__device__ float g_k[NBH * NS * NHD];
__device__ float g_v[NBH * NS * NHD];
__device__ float g_ctx[NBH * NS * NHD];
__device__ float g_attn_scratch[134217728]; // fallback if out buffer excludes attn
__device__ int   g_mask_is_u8;

// ---------------------------------------------------------------------------
// Mask dtype detection: mask row 0 is all-true (global tokens).
// element[1] as byte: u8 -> 1 ; int32 little-endian -> 0 (high byte of elem 0)
// ---------------------------------------------------------------------------
__global__ void detect_mask_kernel(const unsigned char* __restrict__ m) {
    g_mask_is_u8 = (m[1] != 0) ? 1 : 0;
}

// ---------------------------------------------------------------------------
// 128x128x16-tile SGEMM, 256 threads, 8x8 micro-tile. M=4096, N=K=1024.
// C = A @ W + bias
// gatherA:  A read from BHSD-layout tensor  (used by output projection)
// scatterC: C written to BHSD layout        (used by q/k/v projections)
// ---------------------------------------------------------------------------
__global__ void __launch_bounds__(256, 2)
gemm1024_kernel(const float* __restrict__ A,
                const float* __restrict__ W,
                const float* __restrict__ bias,
                float* __restrict__ C,
                int gatherA, int scatterC)
{
    __shared__ float As[16][132];   // [k][m] transposed, padded
    __shared__ float Bs[16][128];   // [k][n]

    const int tid = threadIdx.x;
    const int tx  = tid & 15;       // 16 col groups
    const int ty  = tid >> 4;       // 16 row groups
    const int row0 = blockIdx.y * 128;
    const int col0 = blockIdx.x * 128;

    float acc[8][8] = {};

    for (int k0 = 0; k0 < ND; k0 += 16) {
        // A tile: 128 rows x 16 k  = 512 float4, 2 per thread (transposed store)
        #pragma unroll
        for (int i = 0; i < 2; i++) {
            int idx = i * 256 + tid;
            int r   = idx >> 2;       // m in tile 0..127
            int c4  = idx & 3;        // k float4 group
            int gr  = row0 + r;
            int gk  = k0 + c4 * 4;
            float4 a;
            if (gatherA) {
                int b = gr >> 11;
                int s = gr & (NS - 1);
                int h = gk >> 6;
                int d = gk & 63;
                a = *(const float4*)&A[(((size_t)(b * NH + h)) * NS + s) * NHD + d];
            } else {
                a = *(const float4*)&A[(size_t)gr * ND + gk];
            }
            As[c4 * 4 + 0][r] = a.x;
            As[c4 * 4 + 1][r] = a.y;
            As[c4 * 4 + 2][r] = a.z;
            As[c4 * 4 + 3][r] = a.w;
        }
        // B tile: 16 k x 128 n = 512 float4, 2 per thread
        #pragma unroll
        for (int i = 0; i < 2; i++) {
            int idx = i * 256 + tid;
            int r   = idx >> 5;
            int c4  = idx & 31;
            *(float4*)&Bs[r][c4 * 4] =
                *(const float4*)&W[(size_t)(k0 + r) * ND + col0 + c4 * 4];
        }
        __syncthreads();

        #pragma unroll
        for (int kk = 0; kk < 16; kk++) {
            float4 a0 = *(const float4*)&As[kk][ty * 8];
            float4 a1 = *(const float4*)&As[kk][ty * 8 + 4];
            float4 b0 = *(const float4*)&Bs[kk][tx * 8];
            float4 b1 = *(const float4*)&Bs[kk][tx * 8 + 4];
            float a[8] = {a0.x, a0.y, a0.z, a0.w, a1.x, a1.y, a1.z, a1.w};
            float b[8] = {b0.x, b0.y, b0.z, b0.w, b1.x, b1.y, b1.z, b1.w};
            #pragma unroll
            for (int i = 0; i < 8; i++)
                #pragma unroll
                for (int j = 0; j < 8; j++)
                    acc[i][j] = fmaf(a[i], b[j], acc[i][j]);
        }
        __syncthreads();
    }

    // epilogue
    float4 bia0 = *(const float4*)&bias[col0 + tx * 8];
    float4 bia1 = *(const float4*)&bias[col0 + tx * 8 + 4];
    float bb[8] = {bia0.x, bia0.y, bia0.z, bia0.w, bia1.x, bia1.y, bia1.z, bia1.w};

    #pragma unroll
    for (int i = 0; i < 8; i++) {
        int m = row0 + ty * 8 + i;
        if (scatterC) {
            int b = m >> 11;
            int s = m & (NS - 1);
            #pragma unroll
            for (int j4 = 0; j4 < 2; j4++) {
                int n = col0 + tx * 8 + j4 * 4;
                int h = n >> 6;
                int d = n & 63;
                float4 o = {acc[i][j4*4+0] + bb[j4*4+0],
                            acc[i][j4*4+1] + bb[j4*4+1],
                            acc[i][j4*4+2] + bb[j4*4+2],
                            acc[i][j4*4+3] + bb[j4*4+3]};
                *(float4*)&C[(((size_t)(b * NH + h)) * NS + s) * NHD + d] = o;
            }
        } else {
            int n = col0 + tx * 8;
            float4 o0 = {acc[i][0] + bb[0], acc[i][1] + bb[1],
                         acc[i][2] + bb[2], acc[i][3] + bb[3]};
            float4 o1 = {acc[i][4] + bb[4], acc[i][5] + bb[5],
                         acc[i][6] + bb[6], acc[i][7] + bb[7]};
            *(float4*)&C[(size_t)m * ND + n]     = o0;
            *(float4*)&C[(size_t)m * ND + n + 4] = o1;
        }
    }
}

// ---------------------------------------------------------------------------
// Scores: attn[bh, q, k] = mask ? (Q . K) * scale : -inf
// 128x128 tile per block over K(=HD)=64, 8x8 micro.
// grid = (ktile=16, qtile=16, bh=32), block = 256
// ---------------------------------------------------------------------------
__global__ void __launch_bounds__(256, 2)
score_kernel(const float* __restrict__ qg,
             const float* __restrict__ kg,
             const unsigned char* __restrict__ mask8,
             float* __restrict__ attn)
{
    __shared__ float Qs[16][132];  // [d][q] transposed
    __shared__ float Ks[16][132];  // [d][k] transposed

    const int tid = threadIdx.x;
    const int tx  = tid & 15;
    const int ty  = tid >> 4;
    const int kt  = blockIdx.x;
    const int qt  = blockIdx.y;
    const int bh  = blockIdx.z;

    const float* q = qg + (size_t)bh * NS * NHD;
    const float* k = kg + (size_t)bh * NS * NHD;

    float acc[8][8] = {};

    for (int d0 = 0; d0 < NHD; d0 += 16) {
        #pragma unroll
        for (int i = 0; i < 2; i++) {
            int idx = i * 256 + tid;
            int r   = idx >> 2;
            int c4  = idx & 3;
            float4 a = *(const float4*)&q[(size_t)(qt * 128 + r) * NHD + d0 + c4 * 4];
            Qs[c4*4+0][r] = a.x; Qs[c4*4+1][r] = a.y;
            Qs[c4*4+2][r] = a.z; Qs[c4*4+3][r] = a.w;
            float4 b = *(const float4*)&k[(size_t)(kt * 128 + r) * NHD + d0 + c4 * 4];
            Ks[c4*4+0][r] = b.x; Ks[c4*4+1][r] = b.y;
            Ks[c4*4+2][r] = b.z; Ks[c4*4+3][r] = b.w;
        }
        __syncthreads();

        #pragma unroll
        for (int kk = 0; kk < 16; kk++) {
            float4 a0 = *(const float4*)&Qs[kk][ty * 8];
            float4 a1 = *(const float4*)&Qs[kk][ty * 8 + 4];
            float4 b0 = *(const float4*)&Ks[kk][tx * 8];
            float4 b1 = *(const float4*)&Ks[kk][tx * 8 + 4];
            float a[8] = {a0.x, a0.y, a0.z, a0.w, a1.x, a1.y, a1.z, a1.w};
            float b[8] = {b0.x, b0.y, b0.z, b0.w, b1.x, b1.y, b1.z, b1.w};
            #pragma unroll
            for (int i = 0; i < 8; i++)
                #pragma unroll
                for (int j = 0; j < 8; j++)
                    acc[i][j] = fmaf(a[i], b[j], acc[i][j]);
        }
        __syncthreads();
    }

    const float scale = 0.125f;  // 1/sqrt(64)
    const int use8 = g_mask_is_u8;
    const int* mask32 = (const int*)mask8;

    #pragma unroll
    for (int i = 0; i < 8; i++) {
        int qr = qt * 128 + ty * 8 + i;
        int kc = kt * 128 + tx * 8;
        size_t mbase = (size_t)qr * NS + kc;
        float vals[8];
        if (use8) {
            uint2 m8 = *(const uint2*)(mask8 + mbase);   // 8 bytes, aligned
            unsigned mw[2] = {m8.x, m8.y};
            #pragma unroll
            for (int j = 0; j < 8; j++) {
                bool mv = ((mw[j >> 2] >> ((j & 3) * 8)) & 0xffu) != 0;
                vals[j] = mv ? acc[i][j] * scale : NEG_INF;
            }
        } else {
            int4 m0 = *(const int4*)(mask32 + mbase);
            int4 m1 = *(const int4*)(mask32 + mbase + 4);
            int mm[8] = {m0.x, m0.y, m0.z, m0.w, m1.x, m1.y, m1.z, m1.w};
            #pragma unroll
            for (int j = 0; j < 8; j++)
                vals[j] = mm[j] ? acc[i][j] * scale : NEG_INF;
        }
        float* orow = &attn[((size_t)bh * NS + qr) * NS + kc];
        *(float4*)orow       = make_float4(vals[0], vals[1], vals[2], vals[3]);
        *(float4*)(orow + 4) = make_float4(vals[4], vals[5], vals[6], vals[7]);
    }
}

// ---------------------------------------------------------------------------
// Row softmax over 2048 elements, in place. grid = 65536 rows, block = 256.
// ---------------------------------------------------------------------------
__global__ void softmax_kernel(float* __restrict__ attn)
{
    const size_t row = blockIdx.x;
    float* p = attn + row * (size_t)NS;
    const int tid = threadIdx.x;

    float v[8];
    float mx = NEG_INF;
    #pragma unroll
    for (int i = 0; i < 8; i++) {
        v[i] = p[tid + i * 256];
        mx = fmaxf(mx, v[i]);
    }

    __shared__ float sh[8];
    #pragma unroll
    for (int o = 16; o > 0; o >>= 1)
        mx = fmaxf(mx, __shfl_xor_sync(0xffffffffu, mx, o));
    if ((tid & 31) == 0) sh[tid >> 5] = mx;
    __syncthreads();
    if (tid < 32) {
        float m2 = (tid < 8) ? sh[tid] : NEG_INF;
        #pragma unroll
        for (int o = 4; o > 0; o >>= 1)
            m2 = fmaxf(m2, __shfl_xor_sync(0xffffffffu, m2, o));
        if (tid == 0) sh[0] = m2;
    }
    __syncthreads();
    mx = sh[0];
    __syncthreads();

    float s = 0.0f;
    #pragma unroll
    for (int i = 0; i < 8; i++) {
        v[i] = __expf(v[i] - mx);   // exp(-inf) = 0 for masked entries
        s += v[i];
    }
    #pragma unroll
    for (int o = 16; o > 0; o >>= 1)
        s += __shfl_xor_sync(0xffffffffu, s, o);
    if ((tid & 31) == 0) sh[tid >> 5] = s;
    __syncthreads();
    if (tid < 32) {
        float s2 = (tid < 8) ? sh[tid] : 0.0f;
        #pragma unroll
        for (int o = 4; o > 0; o >>= 1)
            s2 += __shfl_xor_sync(0xffffffffu, s2, o);
        if (tid == 0) sh[0] = s2;
    }
    __syncthreads();
    const float inv = 1.0f / sh[0];

    #pragma unroll
    for (int i = 0; i < 8; i++)
        p[tid + i * 256] = v[i] * inv;
}

// ---------------------------------------------------------------------------
// PV: ctx[bh, q, d] = sum_k attn[bh,q,k] * V[bh,k,d]
// Block tile 128(q) x 64(d), k-tile 32. 128 threads, 8x8 micro.
// grid = (qtile=16, bh=32), block = 128
// ---------------------------------------------------------------------------
__global__ void __launch_bounds__(128, 4)
av_kernel(const float* __restrict__ attn,
          const float* __restrict__ vg,
          float* __restrict__ ctx)
{
    __shared__ float Pt[32][132];  // [k][q] transposed, padded
    __shared__ float Vs[32][64];   // [k][d]

    const int tid = threadIdx.x;   // 128 threads
    const int tx  = tid & 7;       // 8 col groups  (x8 = 64 d)
    const int ty  = tid >> 3;      // 16 row groups (x8 = 128 q)
    const int qt  = blockIdx.x;
    const int bh  = blockIdx.y;

    const float* v    = vg + (size_t)bh * NS * NHD;
    const float* prow = attn + ((size_t)bh * NS + qt * 128) * NS;

    float acc[8][8] = {};

    for (int k0 = 0; k0 < NS; k0 += 32) {
        // attn tile: 128 q x 32 k = 1024 float4, 8 per thread (transposed store)
        #pragma unroll
        for (int i = 0; i < 8; i++) {
            int idx = i * 128 + tid;
            int r   = idx >> 3;       // q row 0..127
            int c4  = idx & 7;        // k float4 group
            float4 a = *(const float4*)&prow[(size_t)r * NS + k0 + c4 * 4];
            Pt[c4*4+0][r] = a.x; Pt[c4*4+1][r] = a.y;
            Pt[c4*4+2][r] = a.z; Pt[c4*4+3][r] = a.w;
        }
        // V tile: 32 k x 64 d = 512 float4, 4 per thread
        #pragma unroll
        for (int i = 0; i < 4; i++) {
            int idx = i * 128 + tid;
            int r   = idx >> 4;
            int c4  = idx & 15;
            *(float4*)&Vs[r][c4 * 4] =
                *(const float4*)&v[(size_t)(k0 + r) * NHD + c4 * 4];
        }
        __syncthreads();

        #pragma unroll
        for (int kk = 0; kk < 32; kk++) {
            float4 a0 = *(const float4*)&Pt[kk][ty * 8];
            float4 a1 = *(const float4*)&Pt[kk][ty * 8 + 4];
            float4 b0 = *(const float4*)&Vs[kk][tx * 8];
            float4 b1 = *(const float4*)&Vs[kk][tx * 8 + 4];
            float a[8] = {a0.x, a0.y, a0.z, a0.w, a1.x, a1.y, a1.z, a1.w};
            float b[8] = {b0.x, b0.y, b0.z, b0.w, b1.x, b1.y, b1.z, b1.w};
            #pragma unroll
            for (int i = 0; i < 8; i++)
                #pragma unroll
                for (int j = 0; j < 8; j++)
                    acc[i][j] = fmaf(a[i], b[j], acc[i][j]);
        }
        __syncthreads();
    }

    #pragma unroll
    for (int i = 0; i < 8; i++) {
        size_t base = ((size_t)bh * NS + qt * 128 + ty * 8 + i) * NHD + tx * 8;
        *(float4*)&ctx[base]     = make_float4(acc[i][0], acc[i][1], acc[i][2], acc[i][3]);
        *(float4*)&ctx[base + 4] = make_float4(acc[i][4], acc[i][5], acc[i][6], acc[i][7]);
    }
}

// ---------------------------------------------------------------------------
extern "C" void kernel_launch(void* const* d_in, const int* in_sizes, int n_in,
                              void* d_out, int out_size)
{
    (void)in_sizes; (void)n_in;

    const float* query = (const float*)d_in[0];
    const float* key   = (const float*)d_in[1];
    const float* value = (const float*)d_in[2];
    const float* Wq    = (const float*)d_in[3];
    const float* bq    = (const float*)d_in[4];
    const float* Wk    = (const float*)d_in[5];
    const float* bk    = (const float*)d_in[6];
    const float* Wv    = (const float*)d_in[7];
    const float* bv    = (const float*)d_in[8];
    const float* Wo    = (const float*)d_in[9];
    const float* bo    = (const float*)d_in[10];
    const unsigned char* mask = (const unsigned char*)d_in[11];

    float* out = (float*)d_out;

    float *qp, *kp, *vp, *ctxp, *attn;
    cudaGetSymbolAddress((void**)&qp,   g_q);
    cudaGetSymbolAddress((void**)&kp,   g_k);
    cudaGetSymbolAddress((void**)&vp,   g_v);
    cudaGetSymbolAddress((void**)&ctxp, g_ctx);

    if ((long long)out_size >= (long long)OUT_ELEMS + ATTN_ELEMS) {
        attn = out + OUT_ELEMS;             // harness output = concat(out, attn)
    } else {
        cudaGetSymbolAddress((void**)&attn, g_attn_scratch);
    }

    detect_mask_kernel<<<1, 1>>>(mask);

    dim3 blk(256);
    dim3 gproj(ND / 128, NM / 128);  // (8, 32)
    gemm1024_kernel<<<gproj, blk>>>(query, Wq, bq, qp, 0, 1);
    gemm1024_kernel<<<gproj, blk>>>(key,   Wk, bk, kp, 0, 1);
    gemm1024_kernel<<<gproj, blk>>>(value, Wv, bv, vp, 0, 1);

    dim3 gscore(NS / 128, NS / 128, NBH);    // (16, 16, 32)
    score_kernel<<<gscore, blk>>>(qp, kp, mask, attn);

    softmax_kernel<<<NBH * NS, blk>>>(attn);

    dim3 gav(NS / 128, NBH);                 // (16, 32)
    av_kernel<<<gav, dim3(128)>>>(attn, vp, ctxp);

    gemm1024_kernel<<<gproj, blk>>>(ctxp, Wo, bo, out, 1, 0);
}